// round 1
// baseline (speedup 1.0000x reference)
#include <cuda_runtime.h>
#include <math.h>

#define B_ 32
#define S_ 128
#define BS_ 4096
#define FEAT_D_ 28224

// ---------------- scratch (module-scope device globals: allowed) ----------------
__device__ float g_feat[(size_t)BS_ * FEAT_D_]; // 462 MB conv output (NHWC flat per row)
__device__ float g_ig[BS_ * 192];               // input gates
__device__ float g_allh[BS_ * 64];              // all hidden states

// ---------------- bool-mask dtype detection ----------------
// masks come from jax bool arrays; harness may store them as u8, i32 or f32.
// For 0/1 int32, bytes at i%4!=0 are all zero. For 1.0f, byte i%4==2 is 0x80.
__device__ __forceinline__ int detect_bool_mode(const unsigned char* p) {
    bool any80 = false, nz = false;
    for (int i = 0; i < 256; i++) {
        unsigned char v = p[i];
        int m = i & 3;
        if (m == 2 && v == 0x80) any80 = true;
        if (m != 0 && v != 0) nz = true;
    }
    if (!nz) return 1;    // int32
    if (any80) return 2;  // float32
    return 0;             // uint8 / bool
}
__device__ __forceinline__ bool get_mask(const void* p, int i, int mode) {
    if (mode == 1) return ((const int*)p)[i] != 0;
    if (mode == 2) return ((const float*)p)[i] != 0.0f;
    return ((const unsigned char*)p)[i] != 0;
}

// ---------------- conv building block ----------------
// 2x2 VALID conv, input planar [ci][Win][Win] in smem, weights HWIO in smem.
// Each thread: 2 pixels x 16 out-channels (32 accumulators) -> 32 FMA per
// (2 input LDS + 4 weight LDS.128). Output planar to smem, or NHWC to global.
template<int Cin, int Cout, int Win, bool GLOBAL>
__device__ __forceinline__ void conv2x2(const float* __restrict__ si,
                                        float* __restrict__ so,
                                        float* __restrict__ go,
                                        const float* __restrict__ wsm,
                                        const float* __restrict__ bsm) {
    constexpr int Wout = Win - 1;
    constexpr int Npix = Wout * Wout;
    constexpr int HWin = Win * Win;
    constexpr int NPAIR = (Npix + 1) / 2;
    constexpr int NG = Cout / 16;
    constexpr int ITEMS = NPAIR * NG;
    constexpr int WSTEP = Cout / 4;

    for (int it = threadIdx.x; it < ITEMS; it += 256) {
        int pr = it % NPAIR, cg = it / NPAIR;
        int p0 = pr, p1 = pr + NPAIR;
        bool has1 = (p1 < Npix);
        int p1c = has1 ? p1 : p0;
        int y0 = p0 / Wout, x0 = p0 - y0 * Wout;
        int y1 = p1c / Wout, x1 = p1c - y1 * Wout;
        int in0 = y0 * Win + x0, in1 = y1 * Win + x1;
        float acc0[16], acc1[16];
#pragma unroll
        for (int j = 0; j < 16; j++) { acc0[j] = 0.f; acc1[j] = 0.f; }
#pragma unroll
        for (int d = 0; d < 4; d++) {
            int dy = d >> 1, dx = d & 1;
            const float* ip0 = si + in0 + dy * Win + dx;
            const float* ip1 = si + in1 + dy * Win + dx;
            const float4* wq = (const float4*)(wsm + (d * Cin) * Cout) + cg * 4;
#pragma unroll 8
            for (int ci = 0; ci < Cin; ci++) {
                float v0 = ip0[ci * HWin];
                float v1 = ip1[ci * HWin];
                float4 wv[4];
                wv[0] = wq[ci * WSTEP + 0];
                wv[1] = wq[ci * WSTEP + 1];
                wv[2] = wq[ci * WSTEP + 2];
                wv[3] = wq[ci * WSTEP + 3];
#pragma unroll
                for (int q = 0; q < 4; q++) {
                    acc0[q * 4 + 0] += v0 * wv[q].x;
                    acc0[q * 4 + 1] += v0 * wv[q].y;
                    acc0[q * 4 + 2] += v0 * wv[q].z;
                    acc0[q * 4 + 3] += v0 * wv[q].w;
                    acc1[q * 4 + 0] += v1 * wv[q].x;
                    acc1[q * 4 + 1] += v1 * wv[q].y;
                    acc1[q * 4 + 2] += v1 * wv[q].z;
                    acc1[q * 4 + 3] += v1 * wv[q].w;
                }
            }
        }
        if constexpr (GLOBAL) {
            float4* g0 = (float4*)(go + p0 * Cout + cg * 16);
#pragma unroll
            for (int q = 0; q < 4; q++) {
                float4 v;
                v.x = fmaxf(acc0[q * 4 + 0] + bsm[cg * 16 + q * 4 + 0], 0.f);
                v.y = fmaxf(acc0[q * 4 + 1] + bsm[cg * 16 + q * 4 + 1], 0.f);
                v.z = fmaxf(acc0[q * 4 + 2] + bsm[cg * 16 + q * 4 + 2], 0.f);
                v.w = fmaxf(acc0[q * 4 + 3] + bsm[cg * 16 + q * 4 + 3], 0.f);
                g0[q] = v;
            }
            if (has1) {
                float4* g1 = (float4*)(go + p1 * Cout + cg * 16);
#pragma unroll
                for (int q = 0; q < 4; q++) {
                    float4 v;
                    v.x = fmaxf(acc1[q * 4 + 0] + bsm[cg * 16 + q * 4 + 0], 0.f);
                    v.y = fmaxf(acc1[q * 4 + 1] + bsm[cg * 16 + q * 4 + 1], 0.f);
                    v.z = fmaxf(acc1[q * 4 + 2] + bsm[cg * 16 + q * 4 + 2], 0.f);
                    v.w = fmaxf(acc1[q * 4 + 3] + bsm[cg * 16 + q * 4 + 3], 0.f);
                    g1[q] = v;
                }
            }
        } else {
#pragma unroll
            for (int j = 0; j < 16; j++) {
                float bj = bsm[cg * 16 + j];
                so[(cg * 16 + j) * Npix + p0] = fmaxf(acc0[j] + bj, 0.f);
            }
            if (has1) {
#pragma unroll
                for (int j = 0; j < 16; j++) {
                    float bj = bsm[cg * 16 + j];
                    so[(cg * 16 + j) * Npix + p1] = fmaxf(acc1[j] + bj, 0.f);
                }
            }
        }
    }
}

// smem layout for conv kernel (floats):
// bufA 15488 (grid 24ch x 576, then reused for c2 32ch x 484)
// bufB 8464  (c1 16ch x 529)
// wb1 1536, wb2 2048, wb3 8192, biases 112
#define CONV_SMEM_FLOATS 35840

__global__ void __launch_bounds__(256) conv_kernel(
    const int* __restrict__ positions, const void* __restrict__ umask,
    const int* __restrict__ tile_type, const int* __restrict__ rpos,
    const void* __restrict__ rmask, const float* __restrict__ reward,
    const float* __restrict__ emb_tile, const float* __restrict__ emb_unit,
    const float* __restrict__ w1, const float* __restrict__ b1,
    const float* __restrict__ w2, const float* __restrict__ b2,
    const float* __restrict__ w3, const float* __restrict__ b3) {
    extern __shared__ float sm[];
    float* bufA = sm;          // 15488
    float* bufB = sm + 15488;  // 8464
    float* wb1 = sm + 23952;   // 1536
    float* wb2 = sm + 25488;   // 2048
    float* wb3 = sm + 27536;   // 8192
    float* sb  = sm + 35728;   // 112 biases: b1[0:16) b2[16:48) b3[48:112)
    int tid = threadIdx.x, bs = blockIdx.x;

    for (int i = tid; i < 1536; i += 256) wb1[i] = w1[i];
    for (int i = tid; i < 2048; i += 256) wb2[i] = w2[i];
    for (int i = tid; i < 8192; i += 256) wb3[i] = w3[i];
    if (tid < 16) sb[tid] = b1[tid];
    else if (tid < 48) sb[tid] = b2[tid - 16];
    else if (tid < 112) sb[tid] = b3[tid - 48];

    // zero planes 4..22 (counts, uemb, relic)
    for (int i = tid; i < 19 * 576; i += 256) bufA[4 * 576 + i] = 0.f;
    // tile-emb planes 0..3, reward plane 23
    float rw = reward[bs];
    for (int p = tid; p < 576; p += 256) {
        int tt = tile_type[bs * 576 + p] * 4;
        bufA[p] = emb_tile[tt];
        bufA[576 + p] = emb_tile[tt + 1];
        bufA[1152 + p] = emb_tile[tt + 2];
        bufA[1728 + p] = emb_tile[tt + 3];
        bufA[23 * 576 + p] = rw;
    }
    __syncthreads();
    // scatter units / relics (shared atomics; tiny)
    if (tid < 32) {
        int mode = detect_bool_mode((const unsigned char*)umask);
        if (get_mask(umask, bs * 32 + tid, mode)) {
            int t = tid >> 4, u = tid & 15;
            int pb = (bs * 32 + tid) * 2;
            int y = positions[pb], x = positions[pb + 1];
            int cell = y * 24 + x;
            atomicAdd(&bufA[(4 + t) * 576 + cell], 0.0625f); // 1/MAXU
#pragma unroll
            for (int e = 0; e < 8; e++)
                atomicAdd(&bufA[(6 + t * 8 + e) * 576 + cell], emb_unit[u * 8 + e]);
        }
    } else if (tid < 38) {
        int r = tid - 32;
        int mode = detect_bool_mode((const unsigned char*)rmask);
        if (get_mask(rmask, bs * 6 + r, mode)) {
            int pb = (bs * 6 + r) * 2;
            int y = rpos[pb], x = rpos[pb + 1];
            atomicAdd(&bufA[22 * 576 + y * 24 + x], 1.0f);
        }
    }
    __syncthreads();
    conv2x2<24, 16, 24, false>(bufA, bufB, nullptr, wb1, sb);
    __syncthreads();
    conv2x2<16, 32, 23, false>(bufB, bufA, nullptr, wb2, sb + 16);
    __syncthreads();
    conv2x2<32, 64, 22, true>(bufA, nullptr, g_feat + (size_t)bs * FEAT_D_, wb3, sb + 48);
}

// ---------------- big GEMM: ig[4096,192] = feat[4096,K] @ Wi[192,K]^T + bi ----------------
__global__ void __launch_bounds__(256) gemm_kernel(const float* __restrict__ Bmat,
                                                   const float* __restrict__ bi) {
    const int K = FEAT_D_;
    __shared__ float As[32][68];
    __shared__ float Bs[32][68];
    int m0 = blockIdx.x * 64, n0 = blockIdx.y * 64;
    int tid = threadIdx.x;
    int tx = tid & 15, ty = tid >> 4;
    int r[2], kq[2];
#pragma unroll
    for (int l = 0; l < 2; l++) { int g = tid + l * 256; r[l] = g >> 3; kq[l] = (g & 7) << 2; }
    const float* A = g_feat;
    float4 pa[2], pb[2];
#pragma unroll
    for (int l = 0; l < 2; l++) {
        pa[l] = *(const float4*)&A[(size_t)(m0 + r[l]) * K + kq[l]];
        pb[l] = *(const float4*)&Bmat[(size_t)(n0 + r[l]) * K + kq[l]];
    }
    float acc[4][4];
#pragma unroll
    for (int i = 0; i < 4; i++)
#pragma unroll
        for (int j = 0; j < 4; j++) acc[i][j] = 0.f;

    for (int kt = 0; kt < K; kt += 32) {
#pragma unroll
        for (int l = 0; l < 2; l++) {
            As[kq[l] + 0][r[l]] = pa[l].x; As[kq[l] + 1][r[l]] = pa[l].y;
            As[kq[l] + 2][r[l]] = pa[l].z; As[kq[l] + 3][r[l]] = pa[l].w;
            Bs[kq[l] + 0][r[l]] = pb[l].x; Bs[kq[l] + 1][r[l]] = pb[l].y;
            Bs[kq[l] + 2][r[l]] = pb[l].z; Bs[kq[l] + 3][r[l]] = pb[l].w;
        }
        __syncthreads();
        int kn = kt + 32;
        if (kn < K) {
#pragma unroll
            for (int l = 0; l < 2; l++) {
                pa[l] = *(const float4*)&A[(size_t)(m0 + r[l]) * K + kn + kq[l]];
                pb[l] = *(const float4*)&Bmat[(size_t)(n0 + r[l]) * K + kn + kq[l]];
            }
        }
#pragma unroll
        for (int k = 0; k < 32; k++) {
            float4 a = *(const float4*)&As[k][ty * 4];
            float4 b = *(const float4*)&Bs[k][tx * 4];
            float av[4] = {a.x, a.y, a.z, a.w};
            float bv[4] = {b.x, b.y, b.z, b.w};
#pragma unroll
            for (int i = 0; i < 4; i++)
#pragma unroll
                for (int j = 0; j < 4; j++) acc[i][j] += av[i] * bv[j];
        }
        __syncthreads();
    }
#pragma unroll
    for (int i = 0; i < 4; i++) {
        int m = m0 + ty * 4 + i;
#pragma unroll
        for (int j = 0; j < 4; j++) {
            int n = n0 + tx * 4 + j;
            g_ig[m * 192 + n] = acc[i][j] + bi[n];
        }
    }
}

// ---------------- GRU scan: one CTA per batch element, Wh rows in registers ----------------
__global__ void __launch_bounds__(192) gru_kernel(const float* __restrict__ h0,
                                                  const float* __restrict__ Wh,
                                                  const float* __restrict__ bn,
                                                  float* __restrict__ hfinal) {
    int b = blockIdx.x, g = threadIdx.x;
    __shared__ float h[64];
    __shared__ float hg[192];
    float w[64];
#pragma unroll
    for (int k = 0; k < 64; k++) w[k] = Wh[g * 64 + k];
    float bnv = (g < 64) ? bn[g] : 0.f;
    if (g < 64) h[g] = h0[b * 64 + g];
    __syncthreads();
    for (int t = 0; t < 128; t++) {
        float acc = 0.f;
#pragma unroll
        for (int k = 0; k < 64; k++) acc += w[k] * h[k];
        hg[g] = acc;
        __syncthreads();
        if (g < 64) {
            const float* igp = g_ig + (b * 128 + t) * 192;
            float rr = 1.f / (1.f + expf(-(igp[g] + hg[g])));
            float zz = 1.f / (1.f + expf(-(igp[64 + g] + hg[64 + g])));
            float nn = tanhf(igp[128 + g] + rr * (hg[128 + g] + bnv));
            float hn = (1.f - zz) * nn + zz * h[g];
            h[g] = hn;
            g_allh[(b * 128 + t) * 64 + g] = hn;
        }
        __syncthreads();
    }
    if (g < 64) hfinal[b * 64 + g] = h[g];
}

// ---------------- heads: actor logits + critic values ----------------
#define HEADS_SMEM_BYTES (14816 * 4)
__global__ void __launch_bounds__(128) heads_kernel(
    const float* __restrict__ Wa1, const float* __restrict__ ba1,
    const float* __restrict__ Wa2, const float* __restrict__ ba2,
    const float* __restrict__ Wc1, const float* __restrict__ bc1,
    const float* __restrict__ Wc2, const float* __restrict__ bc2,
    float* __restrict__ logits, float* __restrict__ values) {
    extern __shared__ float s[];
    float* sWa1 = s;            // 4096
    float* sWc1 = s + 4096;     // 4096
    float* sWa2 = s + 8192;     // 6144
    float* sWc2 = s + 14336;    // 64
    float* sba1 = s + 14400;    // 64
    float* sbc1 = s + 14464;    // 64
    float* sba2 = s + 14528;    // 96
    float* sh   = s + 14624;    // 64
    float* sa   = s + 14688;    // 64
    float* sc   = s + 14752;    // 64
    int tid = threadIdx.x;
    for (int i = tid; i < 4096; i += 128) { sWa1[i] = Wa1[i]; sWc1[i] = Wc1[i]; }
    for (int i = tid; i < 6144; i += 128) sWa2[i] = Wa2[i];
    if (tid < 64) { sWc2[tid] = Wc2[tid]; sba1[tid] = ba1[tid]; sbc1[tid] = bc1[tid]; }
    if (tid < 96) sba2[tid] = ba2[tid];
    float bc2v = bc2[0];
    __syncthreads();
    for (int r = blockIdx.x * 32; r < blockIdx.x * 32 + 32; r++) {
        if (tid < 64) sh[tid] = g_allh[r * 64 + tid];
        __syncthreads();
        {
            int j = tid & 63;
            const float* W = (tid < 64) ? sWa1 : sWc1;
            float acc = 0.f;
#pragma unroll
            for (int i = 0; i < 64; i++) acc += sh[i] * W[i * 64 + j];
            float v = tanhf(acc + ((tid < 64) ? sba1[j] : sbc1[j]));
            if (tid < 64) sa[j] = v; else sc[j] = v;
        }
        __syncthreads();
        if (tid < 96) {
            float acc = sba2[tid];
#pragma unroll
            for (int j = 0; j < 64; j++) acc += sa[j] * sWa2[j * 96 + tid];
            logits[r * 96 + tid] = acc;
        } else if (tid == 96) {
            float acc = bc2v;
#pragma unroll
            for (int j = 0; j < 64; j++) acc += sc[j] * sWc2[j];
            values[r] = acc;
        }
        __syncthreads();
    }
}

// ---------------- launch ----------------
extern "C" void kernel_launch(void* const* d_in, const int* in_sizes, int n_in,
                              void* d_out, int out_size) {
    const int*   positions = (const int*)d_in[0];
    const void*  umask     = d_in[1];
    const int*   tile      = (const int*)d_in[2];
    const int*   rpos      = (const int*)d_in[3];
    const void*  rmask     = d_in[4];
    const float* reward    = (const float*)d_in[5];
    const float* hidden    = (const float*)d_in[6];
    const float* emb_tile  = (const float*)d_in[7];
    const float* emb_unit  = (const float*)d_in[8];
    const float* w1 = (const float*)d_in[9];
    const float* b1 = (const float*)d_in[10];
    const float* w2 = (const float*)d_in[11];
    const float* b2 = (const float*)d_in[12];
    const float* w3 = (const float*)d_in[13];
    const float* b3 = (const float*)d_in[14];
    const float* Wi = (const float*)d_in[15];
    const float* Wh = (const float*)d_in[16];
    const float* bi = (const float*)d_in[17];
    const float* bn = (const float*)d_in[18];
    const float* Wa1 = (const float*)d_in[19];
    const float* ba1 = (const float*)d_in[20];
    const float* Wa2 = (const float*)d_in[21];
    const float* ba2 = (const float*)d_in[22];
    const float* Wc1 = (const float*)d_in[23];
    const float* bc1 = (const float*)d_in[24];
    const float* Wc2 = (const float*)d_in[25];
    const float* bc2 = (const float*)d_in[26];
    float* out = (float*)d_out;

    // output layout: logits[4096*96] | values[4096] | new_hidden[32*64]
    float* out_logits = out;
    float* out_values = out + 393216;
    float* out_hidden = out + 397312;

    const int conv_smem = CONV_SMEM_FLOATS * (int)sizeof(float);
    cudaFuncSetAttribute(conv_kernel, cudaFuncAttributeMaxDynamicSharedMemorySize, conv_smem);
    cudaFuncSetAttribute(heads_kernel, cudaFuncAttributeMaxDynamicSharedMemorySize, HEADS_SMEM_BYTES);

    conv_kernel<<<BS_, 256, conv_smem>>>(positions, umask, tile, rpos, rmask, reward,
                                         emb_tile, emb_unit, w1, b1, w2, b2, w3, b3);
    gemm_kernel<<<dim3(64, 3), 256>>>(Wi, bi);
    gru_kernel<<<32, 192>>>(hidden, Wh, bn, out_hidden);
    heads_kernel<<<128, 128, HEADS_SMEM_BYTES>>>(Wa1, ba1, Wa2, ba2, Wc1, bc1, Wc2, bc2,
                                                 out_logits, out_values);
}

// round 3
// speedup vs baseline: 1.4803x; 1.4803x over previous
#include <cuda_runtime.h>
#include <math.h>

#define B_ 32
#define S_ 128
#define BS_ 4096
#define FEAT_D_ 28224
#define SPLITK 4
#define KSPLIT_LEN (FEAT_D_ / SPLITK)   // 7056

// ---------------- scratch (module-scope device globals: allowed) ----------------
__device__ float g_feat[(size_t)BS_ * FEAT_D_]; // 462 MB conv output (NHWC flat per row)
__device__ float g_ig[BS_ * 192];               // input gates
__device__ float g_part[(size_t)SPLITK * BS_ * 192]; // split-K partials
__device__ float g_allh[BS_ * 64];              // all hidden states

// ---------------- bool-mask dtype detection ----------------
__device__ __forceinline__ int detect_bool_mode(const unsigned char* p) {
    bool any80 = false, nz = false;
    for (int i = 0; i < 256; i++) {
        unsigned char v = p[i];
        int m = i & 3;
        if (m == 2 && v == 0x80) any80 = true;
        if (m != 0 && v != 0) nz = true;
    }
    if (!nz) return 1;    // int32
    if (any80) return 2;  // float32
    return 0;             // uint8 / bool
}
__device__ __forceinline__ bool get_mask(const void* p, int i, int mode) {
    if (mode == 1) return ((const int*)p)[i] != 0;
    if (mode == 2) return ((const float*)p)[i] != 0.0f;
    return ((const unsigned char*)p)[i] != 0;
}

// ---------------- conv building block ----------------
template<int Cin, int Cout, int Win, bool GLOBAL>
__device__ __forceinline__ void conv2x2(const float* __restrict__ si,
                                        float* __restrict__ so,
                                        float* __restrict__ go,
                                        const float* __restrict__ wsm,
                                        const float* __restrict__ bsm) {
    constexpr int Wout = Win - 1;
    constexpr int Npix = Wout * Wout;
    constexpr int HWin = Win * Win;
    constexpr int NPAIR = (Npix + 1) / 2;
    constexpr int NG = Cout / 16;
    constexpr int ITEMS = NPAIR * NG;
    constexpr int WSTEP = Cout / 4;

    for (int it = threadIdx.x; it < ITEMS; it += 256) {
        int pr = it % NPAIR, cg = it / NPAIR;
        int p0 = pr, p1 = pr + NPAIR;
        bool has1 = (p1 < Npix);
        int p1c = has1 ? p1 : p0;
        int y0 = p0 / Wout, x0 = p0 - y0 * Wout;
        int y1 = p1c / Wout, x1 = p1c - y1 * Wout;
        int in0 = y0 * Win + x0, in1 = y1 * Win + x1;
        float acc0[16], acc1[16];
#pragma unroll
        for (int j = 0; j < 16; j++) { acc0[j] = 0.f; acc1[j] = 0.f; }
#pragma unroll
        for (int d = 0; d < 4; d++) {
            int dy = d >> 1, dx = d & 1;
            const float* ip0 = si + in0 + dy * Win + dx;
            const float* ip1 = si + in1 + dy * Win + dx;
            const float4* wq = (const float4*)(wsm + (d * Cin) * Cout) + cg * 4;
#pragma unroll 8
            for (int ci = 0; ci < Cin; ci++) {
                float v0 = ip0[ci * HWin];
                float v1 = ip1[ci * HWin];
                float4 wv[4];
                wv[0] = wq[ci * WSTEP + 0];
                wv[1] = wq[ci * WSTEP + 1];
                wv[2] = wq[ci * WSTEP + 2];
                wv[3] = wq[ci * WSTEP + 3];
#pragma unroll
                for (int q = 0; q < 4; q++) {
                    acc0[q * 4 + 0] += v0 * wv[q].x;
                    acc0[q * 4 + 1] += v0 * wv[q].y;
                    acc0[q * 4 + 2] += v0 * wv[q].z;
                    acc0[q * 4 + 3] += v0 * wv[q].w;
                    acc1[q * 4 + 0] += v1 * wv[q].x;
                    acc1[q * 4 + 1] += v1 * wv[q].y;
                    acc1[q * 4 + 2] += v1 * wv[q].z;
                    acc1[q * 4 + 3] += v1 * wv[q].w;
                }
            }
        }
        if constexpr (GLOBAL) {
            float4* g0 = (float4*)(go + p0 * Cout + cg * 16);
#pragma unroll
            for (int q = 0; q < 4; q++) {
                float4 v;
                v.x = fmaxf(acc0[q * 4 + 0] + bsm[cg * 16 + q * 4 + 0], 0.f);
                v.y = fmaxf(acc0[q * 4 + 1] + bsm[cg * 16 + q * 4 + 1], 0.f);
                v.z = fmaxf(acc0[q * 4 + 2] + bsm[cg * 16 + q * 4 + 2], 0.f);
                v.w = fmaxf(acc0[q * 4 + 3] + bsm[cg * 16 + q * 4 + 3], 0.f);
                g0[q] = v;
            }
            if (has1) {
                float4* g1 = (float4*)(go + p1 * Cout + cg * 16);
#pragma unroll
                for (int q = 0; q < 4; q++) {
                    float4 v;
                    v.x = fmaxf(acc1[q * 4 + 0] + bsm[cg * 16 + q * 4 + 0], 0.f);
                    v.y = fmaxf(acc1[q * 4 + 1] + bsm[cg * 16 + q * 4 + 1], 0.f);
                    v.z = fmaxf(acc1[q * 4 + 2] + bsm[cg * 16 + q * 4 + 2], 0.f);
                    v.w = fmaxf(acc1[q * 4 + 3] + bsm[cg * 16 + q * 4 + 3], 0.f);
                    g1[q] = v;
                }
            }
        } else {
#pragma unroll
            for (int j = 0; j < 16; j++) {
                float bj = bsm[cg * 16 + j];
                so[(cg * 16 + j) * Npix + p0] = fmaxf(acc0[j] + bj, 0.f);
            }
            if (has1) {
#pragma unroll
                for (int j = 0; j < 16; j++) {
                    float bj = bsm[cg * 16 + j];
                    so[(cg * 16 + j) * Npix + p1] = fmaxf(acc1[j] + bj, 0.f);
                }
            }
        }
    }
}

#define CONV_SMEM_FLOATS 35840

__global__ void __launch_bounds__(256) conv_kernel(
    const int* __restrict__ positions, const void* __restrict__ umask,
    const int* __restrict__ tile_type, const int* __restrict__ rpos,
    const void* __restrict__ rmask, const float* __restrict__ reward,
    const float* __restrict__ emb_tile, const float* __restrict__ emb_unit,
    const float* __restrict__ w1, const float* __restrict__ b1,
    const float* __restrict__ w2, const float* __restrict__ b2,
    const float* __restrict__ w3, const float* __restrict__ b3) {
    extern __shared__ float sm[];
    float* bufA = sm;          // 15488
    float* bufB = sm + 15488;  // 8464
    float* wb1 = sm + 23952;   // 1536
    float* wb2 = sm + 25488;   // 2048
    float* wb3 = sm + 27536;   // 8192
    float* sb  = sm + 35728;   // 112
    int tid = threadIdx.x, bs = blockIdx.x;

    for (int i = tid; i < 1536; i += 256) wb1[i] = w1[i];
    for (int i = tid; i < 2048; i += 256) wb2[i] = w2[i];
    for (int i = tid; i < 8192; i += 256) wb3[i] = w3[i];
    if (tid < 16) sb[tid] = b1[tid];
    else if (tid < 48) sb[tid] = b2[tid - 16];
    else if (tid < 112) sb[tid] = b3[tid - 48];

    for (int i = tid; i < 19 * 576; i += 256) bufA[4 * 576 + i] = 0.f;
    float rw = reward[bs];
    for (int p = tid; p < 576; p += 256) {
        int tt = tile_type[bs * 576 + p] * 4;
        bufA[p] = emb_tile[tt];
        bufA[576 + p] = emb_tile[tt + 1];
        bufA[1152 + p] = emb_tile[tt + 2];
        bufA[1728 + p] = emb_tile[tt + 3];
        bufA[23 * 576 + p] = rw;
    }
    __syncthreads();
    if (tid < 32) {
        int mode = detect_bool_mode((const unsigned char*)umask);
        if (get_mask(umask, bs * 32 + tid, mode)) {
            int t = tid >> 4, u = tid & 15;
            int pb = (bs * 32 + tid) * 2;
            int y = positions[pb], x = positions[pb + 1];
            int cell = y * 24 + x;
            atomicAdd(&bufA[(4 + t) * 576 + cell], 0.0625f);
#pragma unroll
            for (int e = 0; e < 8; e++)
                atomicAdd(&bufA[(6 + t * 8 + e) * 576 + cell], emb_unit[u * 8 + e]);
        }
    } else if (tid < 38) {
        int r = tid - 32;
        int mode = detect_bool_mode((const unsigned char*)rmask);
        if (get_mask(rmask, bs * 6 + r, mode)) {
            int pb = (bs * 6 + r) * 2;
            int y = rpos[pb], x = rpos[pb + 1];
            atomicAdd(&bufA[22 * 576 + y * 24 + x], 1.0f);
        }
    }
    __syncthreads();
    conv2x2<24, 16, 24, false>(bufA, bufB, nullptr, wb1, sb);
    __syncthreads();
    conv2x2<16, 32, 23, false>(bufB, bufA, nullptr, wb2, sb + 16);
    __syncthreads();
    conv2x2<32, 64, 22, true>(bufA, nullptr, g_feat + (size_t)bs * FEAT_D_, wb3, sb + 48);
}

// ---------------- TF32 tensor-core GEMM ----------------
// part[kz][4096,192] = feat[4096, kslice] @ Wi[192, kslice]^T
// BM=64, BN=64, BK=16, 256 threads (8 warps, warp grid 2m x 4n, warp tile 32x16).
__device__ __forceinline__ unsigned cvt_tf32(float v) {
    unsigned o;
    asm("cvt.rna.tf32.f32 %0, %1;" : "=r"(o) : "f"(v));
    return o;
}

#define SPAD 72

__global__ void __launch_bounds__(256) gemm_tf32_kernel(const float* __restrict__ Bmat) {
    __shared__ unsigned As[16][SPAD];
    __shared__ unsigned Bs[16][SPAD];
    const int K = FEAT_D_;
    int tid = threadIdx.x;
    int m0 = blockIdx.x * 64, n0 = blockIdx.y * 64;
    int kz = blockIdx.z;
    int kbeg = kz * KSPLIT_LEN;

    int warp = tid >> 5, lane = tid & 31;
    int wm = (warp & 1) * 32;        // warp m offset within tile
    int wn = (warp >> 1) * 16;       // warp n offset
    int grp = lane >> 2, tig = lane & 3;

    int lr = tid >> 2;               // 0..63 row for loading
    int lk = (tid & 3) * 4;          // k quad

    const float* A = g_feat;
    const float* Bp = Bmat;

    float4 pa = *(const float4*)&A[(size_t)(m0 + lr) * K + kbeg + lk];
    float4 pb = *(const float4*)&Bp[(size_t)(n0 + lr) * K + kbeg + lk];

    float acc[2][2][4];
#pragma unroll
    for (int i = 0; i < 2; i++)
#pragma unroll
        for (int j = 0; j < 2; j++)
#pragma unroll
            for (int q = 0; q < 4; q++) acc[i][j][q] = 0.f;

    const int NIT = KSPLIT_LEN / 16;  // 441
    for (int it = 0; it < NIT; it++) {
        As[lk + 0][lr] = cvt_tf32(pa.x);
        As[lk + 1][lr] = cvt_tf32(pa.y);
        As[lk + 2][lr] = cvt_tf32(pa.z);
        As[lk + 3][lr] = cvt_tf32(pa.w);
        Bs[lk + 0][lr] = cvt_tf32(pb.x);
        Bs[lk + 1][lr] = cvt_tf32(pb.y);
        Bs[lk + 2][lr] = cvt_tf32(pb.z);
        Bs[lk + 3][lr] = cvt_tf32(pb.w);
        __syncthreads();
        if (it + 1 < NIT) {
            int kn = kbeg + (it + 1) * 16;
            pa = *(const float4*)&A[(size_t)(m0 + lr) * K + kn + lk];
            pb = *(const float4*)&Bp[(size_t)(n0 + lr) * K + kn + lk];
        }
#pragma unroll
        for (int k8 = 0; k8 < 2; k8++) {
            int kr = k8 * 8;
            unsigned af[2][4], bf[2][2];
#pragma unroll
            for (int mi = 0; mi < 2; mi++) {
                int mb = wm + mi * 16 + grp;
                af[mi][0] = As[kr + tig][mb];
                af[mi][1] = As[kr + tig][mb + 8];
                af[mi][2] = As[kr + tig + 4][mb];
                af[mi][3] = As[kr + tig + 4][mb + 8];
            }
#pragma unroll
            for (int ni = 0; ni < 2; ni++) {
                int nb = wn + ni * 8 + grp;
                bf[ni][0] = Bs[kr + tig][nb];
                bf[ni][1] = Bs[kr + tig + 4][nb];
            }
#pragma unroll
            for (int mi = 0; mi < 2; mi++)
#pragma unroll
                for (int ni = 0; ni < 2; ni++) {
                    asm volatile(
                        "mma.sync.aligned.m16n8k8.row.col.f32.tf32.tf32.f32 "
                        "{%0,%1,%2,%3}, {%4,%5,%6,%7}, {%8,%9}, {%0,%1,%2,%3};"
                        : "+f"(acc[mi][ni][0]), "+f"(acc[mi][ni][1]),
                          "+f"(acc[mi][ni][2]), "+f"(acc[mi][ni][3])
                        : "r"(af[mi][0]), "r"(af[mi][1]), "r"(af[mi][2]), "r"(af[mi][3]),
                          "r"(bf[ni][0]), "r"(bf[ni][1]));
                }
        }
        __syncthreads();
    }

    float* out = g_part + (size_t)kz * (BS_ * 192);
#pragma unroll
    for (int mi = 0; mi < 2; mi++) {
#pragma unroll
        for (int ni = 0; ni < 2; ni++) {
            int col = n0 + wn + ni * 8 + 2 * tig;
            int row0 = m0 + wm + mi * 16 + grp;
            float2 v0 = make_float2(acc[mi][ni][0], acc[mi][ni][1]);
            float2 v1 = make_float2(acc[mi][ni][2], acc[mi][ni][3]);
            *(float2*)&out[(size_t)row0 * 192 + col] = v0;
            *(float2*)&out[(size_t)(row0 + 8) * 192 + col] = v1;
        }
    }
}

__global__ void __launch_bounds__(256) reduce_kernel(const float* __restrict__ bi) {
    int idx = blockIdx.x * 256 + threadIdx.x;
    if (idx >= BS_ * 192) return;
    int n = idx % 192;
    float s = bi[n];
#pragma unroll
    for (int z = 0; z < SPLITK; z++) s += g_part[(size_t)z * (BS_ * 192) + idx];
    g_ig[idx] = s;
}

// ---------------- GRU scan ----------------
__global__ void __launch_bounds__(192) gru_kernel(const float* __restrict__ h0,
                                                  const float* __restrict__ Wh,
                                                  const float* __restrict__ bn,
                                                  float* __restrict__ hfinal) {
    int b = blockIdx.x, g = threadIdx.x;
    __shared__ float h[64];
    __shared__ float hg[192];
    float w[64];
#pragma unroll
    for (int k = 0; k < 64; k++) w[k] = Wh[g * 64 + k];
    float bnv = (g < 64) ? bn[g] : 0.f;
    if (g < 64) h[g] = h0[b * 64 + g];
    __syncthreads();
    for (int t = 0; t < 128; t++) {
        float acc = 0.f;
#pragma unroll
        for (int k = 0; k < 64; k++) acc += w[k] * h[k];
        hg[g] = acc;
        __syncthreads();
        if (g < 64) {
            const float* igp = g_ig + (b * 128 + t) * 192;
            float rr = 1.f / (1.f + expf(-(igp[g] + hg[g])));
            float zz = 1.f / (1.f + expf(-(igp[64 + g] + hg[64 + g])));
            float nn = tanhf(igp[128 + g] + rr * (hg[128 + g] + bnv));
            float hn = (1.f - zz) * nn + zz * h[g];
            h[g] = hn;
            g_allh[(b * 128 + t) * 64 + g] = hn;
        }
        __syncthreads();
    }
    if (g < 64) hfinal[b * 64 + g] = h[g];
}

// ---------------- heads ----------------
#define HEADS_SMEM_BYTES (14816 * 4)
__global__ void __launch_bounds__(128) heads_kernel(
    const float* __restrict__ Wa1, const float* __restrict__ ba1,
    const float* __restrict__ Wa2, const float* __restrict__ ba2,
    const float* __restrict__ Wc1, const float* __restrict__ bc1,
    const float* __restrict__ Wc2, const float* __restrict__ bc2,
    float* __restrict__ logits, float* __restrict__ values) {
    extern __shared__ float s[];
    float* sWa1 = s;
    float* sWc1 = s + 4096;
    float* sWa2 = s + 8192;
    float* sWc2 = s + 14336;
    float* sba1 = s + 14400;
    float* sbc1 = s + 14464;
    float* sba2 = s + 14528;
    float* sh   = s + 14624;
    float* sa   = s + 14688;
    float* sc   = s + 14752;
    int tid = threadIdx.x;
    for (int i = tid; i < 4096; i += 128) { sWa1[i] = Wa1[i]; sWc1[i] = Wc1[i]; }
    for (int i = tid; i < 6144; i += 128) sWa2[i] = Wa2[i];
    if (tid < 64) { sWc2[tid] = Wc2[tid]; sba1[tid] = ba1[tid]; sbc1[tid] = bc1[tid]; }
    if (tid < 96) sba2[tid] = ba2[tid];
    float bc2v = bc2[0];
    __syncthreads();
    for (int r = blockIdx.x * 32; r < blockIdx.x * 32 + 32; r++) {
        if (tid < 64) sh[tid] = g_allh[r * 64 + tid];
        __syncthreads();
        {
            int j = tid & 63;
            const float* W = (tid < 64) ? sWa1 : sWc1;
            float acc = 0.f;
#pragma unroll
            for (int i = 0; i < 64; i++) acc += sh[i] * W[i * 64 + j];
            float v = tanhf(acc + ((tid < 64) ? sba1[j] : sbc1[j]));
            if (tid < 64) sa[j] = v; else sc[j] = v;
        }
        __syncthreads();
        if (tid < 96) {
            float acc = sba2[tid];
#pragma unroll
            for (int j = 0; j < 64; j++) acc += sa[j] * sWa2[j * 96 + tid];
            logits[r * 96 + tid] = acc;
        } else if (tid == 96) {
            float acc = bc2v;
#pragma unroll
            for (int j = 0; j < 64; j++) acc += sc[j] * sWc2[j];
            values[r] = acc;
        }
        __syncthreads();
    }
}

// ---------------- launch ----------------
extern "C" void kernel_launch(void* const* d_in, const int* in_sizes, int n_in,
                              void* d_out, int out_size) {
    const int*   positions = (const int*)d_in[0];
    const void*  umask     = d_in[1];
    const int*   tile      = (const int*)d_in[2];
    const int*   rpos      = (const int*)d_in[3];
    const void*  rmask     = d_in[4];
    const float* reward    = (const float*)d_in[5];
    const float* hidden    = (const float*)d_in[6];
    const float* emb_tile  = (const float*)d_in[7];
    const float* emb_unit  = (const float*)d_in[8];
    const float* w1 = (const float*)d_in[9];
    const float* b1 = (const float*)d_in[10];
    const float* w2 = (const float*)d_in[11];
    const float* b2 = (const float*)d_in[12];
    const float* w3 = (const float*)d_in[13];
    const float* b3 = (const float*)d_in[14];
    const float* Wi = (const float*)d_in[15];
    const float* Wh = (const float*)d_in[16];
    const float* bi = (const float*)d_in[17];
    const float* bn = (const float*)d_in[18];
    const float* Wa1 = (const float*)d_in[19];
    const float* ba1 = (const float*)d_in[20];
    const float* Wa2 = (const float*)d_in[21];
    const float* ba2 = (const float*)d_in[22];
    const float* Wc1 = (const float*)d_in[23];
    const float* bc1 = (const float*)d_in[24];
    const float* Wc2 = (const float*)d_in[25];
    const float* bc2 = (const float*)d_in[26];
    float* out = (float*)d_out;

    float* out_logits = out;
    float* out_values = out + 393216;
    float* out_hidden = out + 397312;

    const int conv_smem = CONV_SMEM_FLOATS * (int)sizeof(float);
    cudaFuncSetAttribute(conv_kernel, cudaFuncAttributeMaxDynamicSharedMemorySize, conv_smem);
    cudaFuncSetAttribute(heads_kernel, cudaFuncAttributeMaxDynamicSharedMemorySize, HEADS_SMEM_BYTES);

    conv_kernel<<<BS_, 256, conv_smem>>>(positions, umask, tile, rpos, rmask, reward,
                                         emb_tile, emb_unit, w1, b1, w2, b2, w3, b3);
    gemm_tf32_kernel<<<dim3(64, 3, SPLITK), 256>>>(Wi);
    reduce_kernel<<<(BS_ * 192 + 255) / 256, 256>>>(bi);
    gru_kernel<<<32, 192>>>(hidden, Wh, bn, out_hidden);
    heads_kernel<<<128, 128, HEADS_SMEM_BYTES>>>(Wa1, ba1, Wa2, ba2, Wc1, bc1, Wc2, bc2,
                                                 out_logits, out_values);
}